// round 9
// baseline (speedup 1.0000x reference)
#include <cuda_runtime.h>
#include <cuda_fp16.h>
#include <mma.h>
#include <cstdint>
#include <cstddef>

using namespace nvcuda;

// Problem constants
constexpr int Bq = 8;
constexpr int T  = 200;
constexpr int U  = 50;
constexpr int D  = 512;    // K
constexpr int V  = 1024;   // N
constexpr int M_ENC  = Bq * T;          // 1600
constexpr int M_TOT  = M_ENC + Bq * U;  // 2000
constexpr int M_PAD  = 2048;

// GEMM tiling (fp16 HMMA): KC=32 halfs per stage, depth-2 cp.async
constexpr int BM  = 64;
constexpr int BN  = 128;
constexpr int KC  = 32;          // halfs per stage (2 k16 steps)
constexpr int NS  = D / KC;      // 16 stages
constexpr int LDH = KC + 8;      // 40 halfs (80 B) row stride, 16B-aligned

// Bcast tiling: 4 t-rows x V/2 per CTA
constexpr int TT = 4;            // t-rows per CTA (divides T=200)
constexpr int VH = V / 2;        // 512 floats per V-half

// Scratch
__device__ float  EP[M_PAD * V];   // [X;pad] @ W^T
__device__ __half Xh[M_PAD * D];   // fp16 [enc;pred;0]
__device__ __half Wh[V * D];       // fp16 W

__device__ __forceinline__ void cp_async16(void* smem_dst, const void* gsrc) {
    uint32_t s = (uint32_t)__cvta_generic_to_shared(smem_dst);
    asm volatile("cp.async.cg.shared.global [%0], [%1], 16;\n" :: "r"(s), "l"(gsrc));
}
__device__ __forceinline__ void cp_commit() {
    asm volatile("cp.async.commit_group;\n" ::);
}

// ---------------------------------------------------------------------------
// Kernel 0: pack [enc;pred;0] and W to fp16 (RN).
// ---------------------------------------------------------------------------
__global__ __launch_bounds__(256)
void pack_half_kernel(const float* __restrict__ enc,
                      const float* __restrict__ pred,
                      const float* __restrict__ W)
{
    const int idx = blockIdx.x * blockDim.x + threadIdx.x;   // float4 index
    constexpr int NX4 = M_PAD * D / 4;   // 262144
    constexpr int NW4 = V * D / 4;       // 131072
    if (idx < NX4) {
        const int row = idx >> 7;            // 128 float4 per row
        const int c   = (idx & 127) * 4;
        float4 v = make_float4(0.f, 0.f, 0.f, 0.f);
        if (row < M_ENC)
            v = *reinterpret_cast<const float4*>(enc + (size_t)row * D + c);
        else if (row < M_TOT)
            v = *reinterpret_cast<const float4*>(pred + (size_t)(row - M_ENC) * D + c);
        __half2 h0 = __floats2half2_rn(v.x, v.y);
        __half2 h1 = __floats2half2_rn(v.z, v.w);
        *reinterpret_cast<__half2*>(Xh + (size_t)idx * 4)     = h0;
        *reinterpret_cast<__half2*>(Xh + (size_t)idx * 4 + 2) = h1;
    } else if (idx < NX4 + NW4) {
        const int j = idx - NX4;
        float4 v = *reinterpret_cast<const float4*>(W + (size_t)j * 4);
        __half2 h0 = __floats2half2_rn(v.x, v.y);
        __half2 h1 = __floats2half2_rn(v.z, v.w);
        *reinterpret_cast<__half2*>(Wh + (size_t)j * 4)     = h0;
        *reinterpret_cast<__half2*>(Wh + (size_t)j * 4 + 2) = h1;
    }
}

// ---------------------------------------------------------------------------
// Kernel 1: EP = Xh @ Wh^T  (fp16 wmma m16n16k16, fp32 accum, double buffer)
// ---------------------------------------------------------------------------
__global__ __launch_bounds__(256, 2)
void joiner_gemm_kernel()
{
    __shared__ __half As[2][BM * LDH];
    __shared__ __half Bs[2][BN * LDH];

    const int m0 = blockIdx.y * BM;
    const int n0 = blockIdx.x * BN;
    const int tid  = threadIdx.x;        // 256
    const int warp = tid >> 5;           // 8 warps: 2(M) x 4(N)
    const int wm   = (warp >> 2) * 32;
    const int wn   = (warp & 3)  * 32;

    wmma::fragment<wmma::accumulator, 16, 16, 16, float> acc[2][2];
#pragma unroll
    for (int i = 0; i < 2; i++)
#pragma unroll
        for (int j = 0; j < 2; j++)
            wmma::fill_fragment(acc[i][j], 0.0f);

    auto load_stage = [&](int ks, int buf) {
        const int k0 = ks * KC;
        {
            const int r = tid >> 2;
            const int c = (tid & 3) * 8;
            cp_async16(&As[buf][r * LDH + c], Xh + (size_t)(m0 + r) * D + k0 + c);
        }
#pragma unroll
        for (int t = 0; t < 2; t++) {
            const int idx = tid + t * 256;
            const int n   = idx >> 2;
            const int c   = (idx & 3) * 8;
            cp_async16(&Bs[buf][n * LDH + c], Wh + (size_t)(n0 + n) * D + k0 + c);
        }
        cp_commit();
    };

    load_stage(0, 0);

    for (int ks = 0; ks < NS; ks++) {
        const int buf = ks & 1;
        if (ks + 1 < NS) {
            load_stage(ks + 1, buf ^ 1);
            asm volatile("cp.async.wait_group 1;\n" ::);
        } else {
            asm volatile("cp.async.wait_group 0;\n" ::);
        }
        __syncthreads();

#pragma unroll
        for (int kk = 0; kk < KC; kk += 16) {
            wmma::fragment<wmma::matrix_a, 16, 16, 16, __half, wmma::row_major> af[2];
            wmma::fragment<wmma::matrix_b, 16, 16, 16, __half, wmma::col_major> bf[2];
#pragma unroll
            for (int i = 0; i < 2; i++)
                wmma::load_matrix_sync(af[i], &As[buf][(wm + i * 16) * LDH + kk], LDH);
#pragma unroll
            for (int j = 0; j < 2; j++)
                wmma::load_matrix_sync(bf[j], &Bs[buf][(wn + j * 16) * LDH + kk], LDH);
#pragma unroll
            for (int i = 0; i < 2; i++)
#pragma unroll
                for (int j = 0; j < 2; j++)
                    wmma::mma_sync(acc[i][j], af[i], bf[j], acc[i][j]);
        }
        __syncthreads();
    }

#pragma unroll
    for (int i = 0; i < 2; i++)
#pragma unroll
        for (int j = 0; j < 2; j++)
            wmma::store_matrix_sync(&EP[(size_t)(m0 + wm + i * 16) * V + (n0 + wn + j * 16)],
                                    acc[i][j], V, wmma::mem_row_major);
}

// ---------------------------------------------------------------------------
// Kernel 2 (v2): 2D-tiled broadcast.
//   CTA = (4 t-rows, V-half). E rows + bias in REGISTERS; only P rows
//   stream from L2 (read traffic 327MB -> ~86MB). 800 uniform CTAs.
//   256 threads = 2 u-lanes x 128 float4-columns.
// ---------------------------------------------------------------------------
__global__ __launch_bounds__(256, 8)
void joiner_bcast_kernel(const float* __restrict__ bias,
                         float* __restrict__ out)
{
    const int bx    = blockIdx.x;            // 0..799
    const int tb    = bx >> 1;                // t-block 0..399
    const int vh    = bx & 1;                 // V-half
    const int bt0   = tb * TT;                // first bt row (never straddles b)
    const int b     = bt0 / T;
    const int tid   = threadIdx.x;
    const int ulane = tid >> 7;               // 0 / 1
    const int col   = tid & 127;              // f4 column within half
    const int voff  = vh * VH + col * 4;

    // E rows + bias pinned in registers
    float4 e[TT];
    {
        float4 bb = *reinterpret_cast<const float4*>(bias + voff);
#pragma unroll
        for (int i = 0; i < TT; i++) {
            float4 t = *reinterpret_cast<const float4*>(EP + (size_t)(bt0 + i) * V + voff);
            t.x += bb.x; t.y += bb.y; t.z += bb.z; t.w += bb.w;
            e[i] = t;
        }
    }

    const float* Pb = EP + (size_t)(M_ENC + b * U + ulane) * V + voff;
    float*       Ob = out + ((size_t)bt0 * U + ulane) * V + voff;

#pragma unroll 5
    for (int uu = 0; uu < U / 2; uu++) {      // 25 iters, u = ulane + 2*uu
        float4 p = *reinterpret_cast<const float4*>(Pb);
        Pb += 2 * V;
#pragma unroll
        for (int i = 0; i < TT; i++) {
            float4 o;
            o.x = e[i].x + p.x;
            o.y = e[i].y + p.y;
            o.z = e[i].z + p.z;
            o.w = e[i].w + p.w;
            *reinterpret_cast<float4*>(Ob + (size_t)i * U * V) = o;
        }
        Ob += 2 * V;
    }
}

// ---------------------------------------------------------------------------
extern "C" void kernel_launch(void* const* d_in, const int* in_sizes, int n_in,
                              void* d_out, int out_size)
{
    const float* enc  = (const float*)d_in[0];   // [B,T,D]
    const float* pred = (const float*)d_in[1];   // [B,U,D]
    const float* W    = (const float*)d_in[2];   // [V,D]
    const float* bias = (const float*)d_in[3];   // [V]
    float* out = (float*)d_out;                  // [B,T,U,V]

    constexpr int NPACK = (M_PAD * D + V * D) / 4;   // 393216
    pack_half_kernel<<<NPACK / 256, 256>>>(enc, pred, W);

    dim3 ggrid(V / BN, M_PAD / BM);                  // 8 x 32 = 256 CTAs
    joiner_gemm_kernel<<<ggrid, 256>>>();

    joiner_bcast_kernel<<<(M_ENC / TT) * 2, 256>>>(bias, out);   // 800 CTAs
}

// round 10
// speedup vs baseline: 1.0752x; 1.0752x over previous
#include <cuda_runtime.h>
#include <cuda_fp16.h>
#include <mma.h>
#include <cstdint>
#include <cstddef>

using namespace nvcuda;

// Problem constants
constexpr int Bq = 8;
constexpr int T  = 200;
constexpr int U  = 50;
constexpr int D  = 512;    // K
constexpr int V  = 1024;   // N
constexpr int M_ENC  = Bq * T;          // 1600
constexpr int M_TOT  = M_ENC + Bq * U;  // 2000
constexpr int M_PAD  = 2048;

// GEMM tiling (fp16 HMMA): KC=64 halfs per stage (128B rows), depth-2
constexpr int BM  = 64;
constexpr int BN  = 128;
constexpr int KC  = 64;          // halfs per stage (4 k16 steps)
constexpr int NS  = D / KC;      // 8 stages
constexpr int LDH = KC + 8;      // 72 halfs (144 B) row stride, 16B-aligned
constexpr int SMEM_DYN = 2 * (BM + BN) * LDH * (int)sizeof(__half);  // 55296 B

// Scratch
__device__ float  EP[M_PAD * V];   // [X;pad] @ W^T
__device__ __half Xh[M_PAD * D];   // fp16 [enc;pred;0]
__device__ __half Wh[V * D];       // fp16 W

__device__ __forceinline__ void cp_async16(void* smem_dst, const void* gsrc) {
    uint32_t s = (uint32_t)__cvta_generic_to_shared(smem_dst);
    asm volatile("cp.async.cg.shared.global [%0], [%1], 16;\n" :: "r"(s), "l"(gsrc));
}
__device__ __forceinline__ void cp_commit() {
    asm volatile("cp.async.commit_group;\n" ::);
}

// ---------------------------------------------------------------------------
// Kernel 0: pack [enc;pred;0] and W to fp16 (RN). 2 float4 per thread (ILP).
// ---------------------------------------------------------------------------
constexpr int NX4 = M_PAD * D / 4;   // 262144
constexpr int NW4 = V * D / 4;       // 131072
constexpr int NP4 = NX4 + NW4;       // 393216

__global__ __launch_bounds__(256)
void pack_half_kernel(const float* __restrict__ enc,
                      const float* __restrict__ pred,
                      const float* __restrict__ W)
{
    const int base = (blockIdx.x * blockDim.x + threadIdx.x) * 2;
#pragma unroll
    for (int it = 0; it < 2; it++) {
        const int idx = base + it;
        if (idx < NX4) {
            const int row = idx >> 7;            // 128 float4 per row
            const int c   = (idx & 127) * 4;
            float4 v = make_float4(0.f, 0.f, 0.f, 0.f);
            if (row < M_ENC)
                v = *reinterpret_cast<const float4*>(enc + (size_t)row * D + c);
            else if (row < M_TOT)
                v = *reinterpret_cast<const float4*>(pred + (size_t)(row - M_ENC) * D + c);
            __half2 h0 = __floats2half2_rn(v.x, v.y);
            __half2 h1 = __floats2half2_rn(v.z, v.w);
            *reinterpret_cast<__half2*>(Xh + (size_t)idx * 4)     = h0;
            *reinterpret_cast<__half2*>(Xh + (size_t)idx * 4 + 2) = h1;
        } else if (idx < NP4) {
            const int j = idx - NX4;
            float4 v = *reinterpret_cast<const float4*>(W + (size_t)j * 4);
            __half2 h0 = __floats2half2_rn(v.x, v.y);
            __half2 h1 = __floats2half2_rn(v.z, v.w);
            *reinterpret_cast<__half2*>(Wh + (size_t)j * 4)     = h0;
            *reinterpret_cast<__half2*>(Wh + (size_t)j * 4 + 2) = h1;
        }
    }
}

// ---------------------------------------------------------------------------
// Kernel 1: EP = Xh @ Wh^T  (fp16 wmma m16n16k16, fp32 accum, KC=64 stages)
// ---------------------------------------------------------------------------
__global__ __launch_bounds__(256, 2)
void joiner_gemm_kernel()
{
    extern __shared__ __half hsm[];
    __half* As = hsm;                       // [2][BM*LDH]
    __half* Bs = hsm + 2 * BM * LDH;        // [2][BN*LDH]

    const int m0 = blockIdx.y * BM;
    const int n0 = blockIdx.x * BN;
    const int tid  = threadIdx.x;        // 256
    const int warp = tid >> 5;           // 8 warps: 2(M) x 4(N)
    const int wm   = (warp >> 2) * 32;
    const int wn   = (warp & 3)  * 32;

    wmma::fragment<wmma::accumulator, 16, 16, 16, float> acc[2][2];
#pragma unroll
    for (int i = 0; i < 2; i++)
#pragma unroll
        for (int j = 0; j < 2; j++)
            wmma::fill_fragment(acc[i][j], 0.0f);

    auto load_stage = [&](int ks, int buf) {
        const int k0 = ks * KC;
        // A: 64 rows x 64 halfs (128B) = 512 x 16B chunks, 2/thread
#pragma unroll
        for (int t = 0; t < 2; t++) {
            const int idx = tid + t * 256;
            const int r   = idx >> 3;            // 8 chunks per row
            const int c   = (idx & 7) * 8;       // half offset
            cp_async16(&As[buf * BM * LDH + r * LDH + c],
                       Xh + (size_t)(m0 + r) * D + k0 + c);
        }
        // B: 128 rows x 64 halfs = 1024 chunks, 4/thread
#pragma unroll
        for (int t = 0; t < 4; t++) {
            const int idx = tid + t * 256;
            const int n   = idx >> 3;
            const int c   = (idx & 7) * 8;
            cp_async16(&Bs[buf * BN * LDH + n * LDH + c],
                       Wh + (size_t)(n0 + n) * D + k0 + c);
        }
        cp_commit();
    };

    load_stage(0, 0);

    for (int ks = 0; ks < NS; ks++) {
        const int buf = ks & 1;
        if (ks + 1 < NS) {
            load_stage(ks + 1, buf ^ 1);
            asm volatile("cp.async.wait_group 1;\n" ::);
        } else {
            asm volatile("cp.async.wait_group 0;\n" ::);
        }
        __syncthreads();

#pragma unroll
        for (int kk = 0; kk < KC; kk += 16) {
            wmma::fragment<wmma::matrix_a, 16, 16, 16, __half, wmma::row_major> af[2];
            wmma::fragment<wmma::matrix_b, 16, 16, 16, __half, wmma::col_major> bf[2];
#pragma unroll
            for (int i = 0; i < 2; i++)
                wmma::load_matrix_sync(af[i], &As[buf * BM * LDH + (wm + i * 16) * LDH + kk], LDH);
#pragma unroll
            for (int j = 0; j < 2; j++)
                wmma::load_matrix_sync(bf[j], &Bs[buf * BN * LDH + (wn + j * 16) * LDH + kk], LDH);
#pragma unroll
            for (int i = 0; i < 2; i++)
#pragma unroll
                for (int j = 0; j < 2; j++)
                    wmma::mma_sync(acc[i][j], af[i], bf[j], acc[i][j]);
        }
        __syncthreads();
    }

#pragma unroll
    for (int i = 0; i < 2; i++)
#pragma unroll
        for (int j = 0; j < 2; j++)
            wmma::store_matrix_sync(&EP[(size_t)(m0 + wm + i * 16) * V + (n0 + wn + j * 16)],
                                    acc[i][j], V, wmma::mem_row_major);
}

// ---------------------------------------------------------------------------
// Kernel 2: out[b,t,u,v] = EP[b*T+t, v] + EP[1600 + b*U+u, v] + bias[v]
//   Proven optimum (R1/R4/R8): one CTA per (b,t), plain STG.128, unroll 5.
// ---------------------------------------------------------------------------
__global__ __launch_bounds__(256, 8)
void joiner_bcast_kernel(const float* __restrict__ bias,
                         float* __restrict__ out)
{
    const int bt  = blockIdx.x;          // 0..1599
    const int b   = bt / T;
    const int tid = threadIdx.x;         // 256 threads * 4 floats = V

    float4 e  = *reinterpret_cast<const float4*>(EP + (size_t)bt * V + tid * 4);
    float4 bb = *reinterpret_cast<const float4*>(bias + tid * 4);
    e.x += bb.x; e.y += bb.y; e.z += bb.z; e.w += bb.w;

    const float* Pbase = EP + (size_t)(M_ENC + b * U) * V + tid * 4;
    float*       Obase = out + (size_t)bt * U * V + tid * 4;

#pragma unroll 5
    for (int u = 0; u < U; u++) {
        float4 p = *reinterpret_cast<const float4*>(Pbase + (size_t)u * V);
        float4 o;
        o.x = e.x + p.x;
        o.y = e.y + p.y;
        o.z = e.z + p.z;
        o.w = e.w + p.w;
        *reinterpret_cast<float4*>(Obase + (size_t)u * V) = o;
    }
}

// ---------------------------------------------------------------------------
extern "C" void kernel_launch(void* const* d_in, const int* in_sizes, int n_in,
                              void* d_out, int out_size)
{
    const float* enc  = (const float*)d_in[0];   // [B,T,D]
    const float* pred = (const float*)d_in[1];   // [B,U,D]
    const float* W    = (const float*)d_in[2];   // [V,D]
    const float* bias = (const float*)d_in[3];   // [V]
    float* out = (float*)d_out;                  // [B,T,U,V]

    // idempotent, capture-safe host attribute set (54 KB dynamic smem)
    cudaFuncSetAttribute(joiner_gemm_kernel,
                         cudaFuncAttributeMaxDynamicSharedMemorySize, SMEM_DYN);

    pack_half_kernel<<<NP4 / 512, 256>>>(enc, pred, W);          // 768 CTAs

    dim3 ggrid(V / BN, M_PAD / BM);                              // 8 x 32 = 256 CTAs
    joiner_gemm_kernel<<<ggrid, 256, SMEM_DYN>>>();

    joiner_bcast_kernel<<<M_ENC, 256>>>(bias, out);
}

// round 11
// speedup vs baseline: 1.1343x; 1.0550x over previous
#include <cuda_runtime.h>
#include <cuda_fp16.h>
#include <mma.h>
#include <cstdint>
#include <cstddef>

using namespace nvcuda;

// Problem constants
constexpr int Bq = 8;
constexpr int T  = 200;
constexpr int U  = 50;
constexpr int D  = 512;    // K
constexpr int V  = 1024;   // N
constexpr int M_ENC  = Bq * T;          // 1600
constexpr int M_TOT  = M_ENC + Bq * U;  // 2000
constexpr int M_PAD  = 2048;

// GEMM tiling (fp16 HMMA): KC=64 halfs per stage (128B rows), depth-2
constexpr int BM  = 64;
constexpr int BN  = 128;
constexpr int KC  = 64;          // halfs per stage (4 k16 steps)
constexpr int NS  = D / KC;      // 8 stages
constexpr int LDH = KC + 8;      // 72 halfs (144 B) row stride, 16B-aligned
constexpr int SMEM_DYN = 2 * (BM + BN) * LDH * (int)sizeof(__half);  // 55296 B

// Bcast: 4 consecutive bt rows per 1024-thread CTA (R4 store pattern kept)
constexpr int TT = 4;

// Scratch
__device__ float  EP[M_PAD * V];   // [X;pad] @ W^T
__device__ __half Xh[M_PAD * D];   // fp16 [enc;pred;0]
__device__ __half Wh[V * D];       // fp16 W

__device__ __forceinline__ void cp_async16(void* smem_dst, const void* gsrc) {
    uint32_t s = (uint32_t)__cvta_generic_to_shared(smem_dst);
    asm volatile("cp.async.cg.shared.global [%0], [%1], 16;\n" :: "r"(s), "l"(gsrc));
}
__device__ __forceinline__ void cp_commit() {
    asm volatile("cp.async.commit_group;\n" ::);
}
__device__ __forceinline__ uint4 pack8_to_half(float4 a, float4 b) {
    __half2 h0 = __floats2half2_rn(a.x, a.y);
    __half2 h1 = __floats2half2_rn(a.z, a.w);
    __half2 h2 = __floats2half2_rn(b.x, b.y);
    __half2 h3 = __floats2half2_rn(b.z, b.w);
    uint4 r;
    r.x = *reinterpret_cast<uint32_t*>(&h0);
    r.y = *reinterpret_cast<uint32_t*>(&h1);
    r.z = *reinterpret_cast<uint32_t*>(&h2);
    r.w = *reinterpret_cast<uint32_t*>(&h3);
    return r;
}

// ---------------------------------------------------------------------------
// Kernel 0: pack [enc;pred;0] and W to fp16. Each thread: 8 floats -> one
// 16-byte half store.
// ---------------------------------------------------------------------------
constexpr int NX8 = M_PAD * D / 8;   // 131072 (8-float groups)
constexpr int NW8 = V * D / 8;       // 65536
constexpr int NP8 = NX8 + NW8;       // 196608

__global__ __launch_bounds__(256)
void pack_half_kernel(const float* __restrict__ enc,
                      const float* __restrict__ pred,
                      const float* __restrict__ W)
{
    const int idx = blockIdx.x * blockDim.x + threadIdx.x;   // 8-float group
    if (idx < NX8) {
        const int row = idx >> 6;            // 64 groups per 512-float row
        const int c   = (idx & 63) * 8;
        float4 a = make_float4(0.f, 0.f, 0.f, 0.f), b = a;
        if (row < M_ENC) {
            const float* s = enc + (size_t)row * D + c;
            a = *reinterpret_cast<const float4*>(s);
            b = *reinterpret_cast<const float4*>(s + 4);
        } else if (row < M_TOT) {
            const float* s = pred + (size_t)(row - M_ENC) * D + c;
            a = *reinterpret_cast<const float4*>(s);
            b = *reinterpret_cast<const float4*>(s + 4);
        }
        *reinterpret_cast<uint4*>(Xh + (size_t)idx * 8) = pack8_to_half(a, b);
    } else if (idx < NP8) {
        const int j = idx - NX8;
        const float* s = W + (size_t)j * 8;
        float4 a = *reinterpret_cast<const float4*>(s);
        float4 b = *reinterpret_cast<const float4*>(s + 4);
        *reinterpret_cast<uint4*>(Wh + (size_t)j * 8) = pack8_to_half(a, b);
    }
}

// ---------------------------------------------------------------------------
// Kernel 1: EP = Xh @ Wh^T  (fp16 wmma m16n16k16, fp32 accum, KC=64 stages)
//   Unchanged from R10 (proven: ~10us incl. gaps).
// ---------------------------------------------------------------------------
__global__ __launch_bounds__(256, 2)
void joiner_gemm_kernel()
{
    extern __shared__ __half hsm[];
    __half* As = hsm;                       // [2][BM*LDH]
    __half* Bs = hsm + 2 * BM * LDH;        // [2][BN*LDH]

    const int m0 = blockIdx.y * BM;
    const int n0 = blockIdx.x * BN;
    const int tid  = threadIdx.x;        // 256
    const int warp = tid >> 5;           // 8 warps: 2(M) x 4(N)
    const int wm   = (warp >> 2) * 32;
    const int wn   = (warp & 3)  * 32;

    wmma::fragment<wmma::accumulator, 16, 16, 16, float> acc[2][2];
#pragma unroll
    for (int i = 0; i < 2; i++)
#pragma unroll
        for (int j = 0; j < 2; j++)
            wmma::fill_fragment(acc[i][j], 0.0f);

    auto load_stage = [&](int ks, int buf) {
        const int k0 = ks * KC;
#pragma unroll
        for (int t = 0; t < 2; t++) {
            const int idx = tid + t * 256;
            const int r   = idx >> 3;
            const int c   = (idx & 7) * 8;
            cp_async16(&As[buf * BM * LDH + r * LDH + c],
                       Xh + (size_t)(m0 + r) * D + k0 + c);
        }
#pragma unroll
        for (int t = 0; t < 4; t++) {
            const int idx = tid + t * 256;
            const int n   = idx >> 3;
            const int c   = (idx & 7) * 8;
            cp_async16(&Bs[buf * BN * LDH + n * LDH + c],
                       Wh + (size_t)(n0 + n) * D + k0 + c);
        }
        cp_commit();
    };

    load_stage(0, 0);

    for (int ks = 0; ks < NS; ks++) {
        const int buf = ks & 1;
        if (ks + 1 < NS) {
            load_stage(ks + 1, buf ^ 1);
            asm volatile("cp.async.wait_group 1;\n" ::);
        } else {
            asm volatile("cp.async.wait_group 0;\n" ::);
        }
        __syncthreads();

#pragma unroll
        for (int kk = 0; kk < KC; kk += 16) {
            wmma::fragment<wmma::matrix_a, 16, 16, 16, __half, wmma::row_major> af[2];
            wmma::fragment<wmma::matrix_b, 16, 16, 16, __half, wmma::col_major> bf[2];
#pragma unroll
            for (int i = 0; i < 2; i++)
                wmma::load_matrix_sync(af[i], &As[buf * BM * LDH + (wm + i * 16) * LDH + kk], LDH);
#pragma unroll
            for (int j = 0; j < 2; j++)
                wmma::load_matrix_sync(bf[j], &Bs[buf * BN * LDH + (wn + j * 16) * LDH + kk], LDH);
#pragma unroll
            for (int i = 0; i < 2; i++)
#pragma unroll
                for (int j = 0; j < 2; j++)
                    wmma::mma_sync(acc[i][j], af[i], bf[j], acc[i][j]);
        }
        __syncthreads();
    }

#pragma unroll
    for (int i = 0; i < 2; i++)
#pragma unroll
        for (int j = 0; j < 2; j++)
            wmma::store_matrix_sync(&EP[(size_t)(m0 + wm + i * 16) * V + (n0 + wn + j * 16)],
                                    acc[i][j], V, wmma::mem_row_major);
}

// ---------------------------------------------------------------------------
// Kernel 2 (v3): 4 bt rows per 1024-thread CTA.
//   Thread (r, c) keeps the per-thread store pattern of the proven R4 kernel
//   (single contiguous row stream, 4KB steps), but the 4 row-groups share each
//   P[u] line via L1 -> L2 read traffic drops 327MB -> ~82MB (LTS decongest).
// ---------------------------------------------------------------------------
__global__ __launch_bounds__(1024, 2)
void joiner_bcast_kernel(const float* __restrict__ bias,
                         float* __restrict__ out)
{
    const int bt0 = blockIdx.x * TT;     // 400 CTAs; T%4==0 -> no b straddle
    const int b   = bt0 / T;
    const int tid = threadIdx.x;         // 1024
    const int r   = tid >> 8;            // row 0..3
    const int c4  = (tid & 255) * 4;     // f4 column

    float4 e  = *reinterpret_cast<const float4*>(EP + (size_t)(bt0 + r) * V + c4);
    float4 bb = *reinterpret_cast<const float4*>(bias + c4);
    e.x += bb.x; e.y += bb.y; e.z += bb.z; e.w += bb.w;

    const float* Pbase = EP + (size_t)(M_ENC + b * U) * V + c4;
    float*       Obase = out + (size_t)(bt0 + r) * U * V + c4;

#pragma unroll 5
    for (int u = 0; u < U; u++) {
        float4 p = *reinterpret_cast<const float4*>(Pbase + (size_t)u * V);
        float4 o;
        o.x = e.x + p.x;
        o.y = e.y + p.y;
        o.z = e.z + p.z;
        o.w = e.w + p.w;
        *reinterpret_cast<float4*>(Obase + (size_t)u * V) = o;
    }
}

// ---------------------------------------------------------------------------
extern "C" void kernel_launch(void* const* d_in, const int* in_sizes, int n_in,
                              void* d_out, int out_size)
{
    const float* enc  = (const float*)d_in[0];   // [B,T,D]
    const float* pred = (const float*)d_in[1];   // [B,U,D]
    const float* W    = (const float*)d_in[2];   // [V,D]
    const float* bias = (const float*)d_in[3];   // [V]
    float* out = (float*)d_out;                  // [B,T,U,V]

    cudaFuncSetAttribute(joiner_gemm_kernel,
                         cudaFuncAttributeMaxDynamicSharedMemorySize, SMEM_DYN);

    pack_half_kernel<<<NP8 / 256, 256>>>(enc, pred, W);          // 768 CTAs

    dim3 ggrid(V / BN, M_PAD / BM);                              // 8 x 32 = 256 CTAs
    joiner_gemm_kernel<<<ggrid, 256, SMEM_DYN>>>();

    joiner_bcast_kernel<<<M_ENC / TT, 1024>>>(bias, out);        // 400 CTAs
}